// round 7
// baseline (speedup 1.0000x reference)
#include <cuda_runtime.h>
#include <cuda_bf16.h>
#include <cstddef>

// Problem constants (fixed by the dataset)
#define N_NODES 100000
#define N_EDGES 1600000
#define D       128
#define ND      ((size_t)N_NODES * D)

#define SCAN_B    1024
#define N_SCANBLK ((N_NODES + SCAN_B - 1) / SCAN_B)   // 98

#define TILE_ROWS 32      // dst nodes per block (100000 % 32 == 0 -> exact grid)

// ---------------------------------------------------------------------------
// Scratch (__device__ globals; no allocation allowed anywhere)
// ---------------------------------------------------------------------------
__device__ __align__(16) float g_inv[N_NODES];        // 1/max(outdeg,1)
__device__ __align__(16) int   g_counts[N_NODES];     // in-degree histogram (by dst)
__device__ __align__(16) int   g_cursor[N_NODES];     // CSR fill cursors
__device__ __align__(16) int   g_rowptr[N_NODES + 1]; // CSR row pointers (by dst)
__device__ __align__(16) int   g_bsums[N_SCANBLK];    // scan partials
__device__ __align__(16) int   g_eidx[N_EDGES];       // CSR column indices (src node)
__device__ __align__(16) float g_z1[ND];              // layer-1 output (pre-scaled by inv)

// ---------------------------------------------------------------------------
// f32x2 packed-FMA helpers (sm_103a FFMA2 — only reachable via PTX)
// ---------------------------------------------------------------------------
__device__ __forceinline__ unsigned long long pack2(float lo, float hi) {
    unsigned long long r;
    asm("mov.b64 %0, {%1, %2};" : "=l"(r) : "f"(lo), "f"(hi));
    return r;
}
__device__ __forceinline__ void fma2(unsigned long long& d,
                                     unsigned long long a, unsigned long long b) {
    asm("fma.rn.f32x2 %0, %1, %2, %0;" : "+l"(d) : "l"(a), "l"(b));
}
__device__ __forceinline__ float2 unpack2(unsigned long long v) {
    float lo, hi;
    asm("mov.b64 {%0, %1}, %2;" : "=f"(lo), "=f"(hi) : "l"(v));
    return make_float2(lo, hi);
}

// ---------------------------------------------------------------------------
// CSR build kernels
// ---------------------------------------------------------------------------
__global__ void zero_small_kernel(float* __restrict__ inv,
                                  int* __restrict__ counts,
                                  int* __restrict__ cursor) {
    int i = blockIdx.x * blockDim.x + threadIdx.x;
    if (i < N_NODES) { inv[i] = 0.f; counts[i] = 0; cursor[i] = 0; }
}

__global__ void hist_kernel(const int* __restrict__ src, const int* __restrict__ dst,
                            float* __restrict__ deg, int* __restrict__ counts) {
    int e = blockIdx.x * blockDim.x + threadIdx.x;
    if (e < N_EDGES) {
        atomicAdd(&deg[src[e]], 1.0f);
        atomicAdd(&counts[dst[e]], 1);
    }
}

__global__ void inv_kernel(float* __restrict__ deg) {
    int i = blockIdx.x * blockDim.x + threadIdx.x;
    if (i < N_NODES) deg[i] = 1.0f / fmaxf(deg[i], 1.0f);
}

__global__ __launch_bounds__(SCAN_B)
void scan_block_kernel(const int* __restrict__ counts, int* __restrict__ rowptr,
                       int* __restrict__ bsums) {
    __shared__ int s[SCAN_B];
    int i = blockIdx.x * SCAN_B + threadIdx.x;
    int v = (i < N_NODES) ? counts[i] : 0;
    s[threadIdx.x] = v;
    __syncthreads();
    #pragma unroll
    for (int off = 1; off < SCAN_B; off <<= 1) {
        int t = (threadIdx.x >= off) ? s[threadIdx.x - off] : 0;
        __syncthreads();
        s[threadIdx.x] += t;
        __syncthreads();
    }
    if (i < N_NODES) rowptr[i + 1] = s[threadIdx.x];
    if (threadIdx.x == SCAN_B - 1) bsums[blockIdx.x] = s[SCAN_B - 1];
}

__global__ __launch_bounds__(128)
void scan_sums_kernel(int* __restrict__ bsums) {
    __shared__ int s[128];
    int v = (threadIdx.x < N_SCANBLK) ? bsums[threadIdx.x] : 0;
    s[threadIdx.x] = v;
    __syncthreads();
    #pragma unroll
    for (int off = 1; off < 128; off <<= 1) {
        int t = (threadIdx.x >= off) ? s[threadIdx.x - off] : 0;
        __syncthreads();
        s[threadIdx.x] += t;
        __syncthreads();
    }
    if (threadIdx.x < N_SCANBLK)
        bsums[threadIdx.x] = (threadIdx.x > 0) ? s[threadIdx.x - 1] : 0;
}

__global__ __launch_bounds__(SCAN_B)
void scan_add_kernel(int* __restrict__ rowptr, const int* __restrict__ bsums) {
    int i = blockIdx.x * SCAN_B + threadIdx.x;
    if (i < N_NODES) rowptr[i + 1] += bsums[blockIdx.x];
    if (i == 0) rowptr[0] = 0;
}

__global__ void csr_fill_kernel(const int* __restrict__ src, const int* __restrict__ dst,
                                const int* __restrict__ rowptr, int* __restrict__ cursor,
                                int* __restrict__ eidx) {
    int e = blockIdx.x * blockDim.x + threadIdx.x;
    if (e < N_EDGES) {
        int d = dst[e];
        int pos = rowptr[d] + atomicAdd(&cursor[d], 1);
        eidx[pos] = src[e];
    }
}

// ---------------------------------------------------------------------------
// Fused layer: gather (CSR, optional per-src scale) -> smem tile
//              -> FFMA2 GEMM -> bias -> PReLU -> optional per-dst rowscale
// Block = 128 threads = 4 warps; 32 dst rows; each warp gathers 8 rows.
// ---------------------------------------------------------------------------
template <bool EDGE_SCALE, bool ROW_SCALE>
__global__ __launch_bounds__(128)
void fused_layer_kernel(const float* __restrict__ h,        // source features [N,D]
                        const int*   __restrict__ rowptr,
                        const int*   __restrict__ eidx,
                        const float* __restrict__ inv,      // per-node 1/outdeg
                        const float* __restrict__ W,
                        const float* __restrict__ b,
                        const float* __restrict__ prelu_a,
                        float*       __restrict__ out) {
    __shared__ __align__(16) float sA[TILE_ROWS][D];

    const int tid  = threadIdx.x;
    const int lane = tid & 31;
    const int wid  = tid >> 5;
    const int base = blockIdx.x * TILE_ROWS;
    const float4* h4 = reinterpret_cast<const float4*>(h);

    // ---- Phase 1: gather — each of the 4 warps fills 8 rows of sA ----
    #pragma unroll 1
    for (int i = 0; i < TILE_ROWS / 4; i++) {   // 8 rows per warp (FIXED bound)
        int row  = wid * (TILE_ROWS / 4) + i;
        int node = base + row;
        int beg = __ldg(&rowptr[node]);
        int end = __ldg(&rowptr[node + 1]);

        float4 acc = make_float4(0.f, 0.f, 0.f, 0.f);
        for (int e = beg; e < end; e += 32) {
            int cnt = min(32, end - e);
            int   s  = (lane < cnt) ? __ldg(&eidx[e + lane]) : 0;
            float sc = 0.f;
            if (EDGE_SCALE) sc = (lane < cnt) ? __ldg(&inv[s]) : 0.f;

            int j = 0;
            for (; j + 4 <= cnt; j += 4) {
                int s0 = __shfl_sync(0xFFFFFFFFu, s, j + 0);
                int s1 = __shfl_sync(0xFFFFFFFFu, s, j + 1);
                int s2 = __shfl_sync(0xFFFFFFFFu, s, j + 2);
                int s3 = __shfl_sync(0xFFFFFFFFu, s, j + 3);
                float4 v0 = __ldg(&h4[(size_t)s0 * 32 + lane]);
                float4 v1 = __ldg(&h4[(size_t)s1 * 32 + lane]);
                float4 v2 = __ldg(&h4[(size_t)s2 * 32 + lane]);
                float4 v3 = __ldg(&h4[(size_t)s3 * 32 + lane]);
                if (EDGE_SCALE) {
                    float c0 = __shfl_sync(0xFFFFFFFFu, sc, j + 0);
                    float c1 = __shfl_sync(0xFFFFFFFFu, sc, j + 1);
                    float c2 = __shfl_sync(0xFFFFFFFFu, sc, j + 2);
                    float c3 = __shfl_sync(0xFFFFFFFFu, sc, j + 3);
                    acc.x = fmaf(v0.x, c0, fmaf(v1.x, c1, fmaf(v2.x, c2, fmaf(v3.x, c3, acc.x))));
                    acc.y = fmaf(v0.y, c0, fmaf(v1.y, c1, fmaf(v2.y, c2, fmaf(v3.y, c3, acc.y))));
                    acc.z = fmaf(v0.z, c0, fmaf(v1.z, c1, fmaf(v2.z, c2, fmaf(v3.z, c3, acc.z))));
                    acc.w = fmaf(v0.w, c0, fmaf(v1.w, c1, fmaf(v2.w, c2, fmaf(v3.w, c3, acc.w))));
                } else {
                    acc.x += v0.x + v1.x + v2.x + v3.x;
                    acc.y += v0.y + v1.y + v2.y + v3.y;
                    acc.z += v0.z + v1.z + v2.z + v3.z;
                    acc.w += v0.w + v1.w + v2.w + v3.w;
                }
            }
            for (; j < cnt; j++) {
                int ss = __shfl_sync(0xFFFFFFFFu, s, j);
                float4 v = __ldg(&h4[(size_t)ss * 32 + lane]);
                if (EDGE_SCALE) {
                    float cc = __shfl_sync(0xFFFFFFFFu, sc, j);
                    acc.x = fmaf(v.x, cc, acc.x);
                    acc.y = fmaf(v.y, cc, acc.y);
                    acc.z = fmaf(v.z, cc, acc.z);
                    acc.w = fmaf(v.w, cc, acc.w);
                } else {
                    acc.x += v.x; acc.y += v.y; acc.z += v.z; acc.w += v.w;
                }
            }
        }
        *reinterpret_cast<float4*>(&sA[row][lane * 4]) = acc;
    }
    __syncthreads();

    // ---- Phase 2: GEMM (thread = output column tid), FFMA2 over k-pairs ----
    unsigned long long acc2[TILE_ROWS];
    #pragma unroll
    for (int r = 0; r < TILE_ROWS; r++) acc2[r] = pack2(0.f, 0.f);

    #pragma unroll 4
    for (int k = 0; k < D; k += 4) {
        float w0 = W[(k + 0) * D + tid];
        float w1 = W[(k + 1) * D + tid];
        float w2 = W[(k + 2) * D + tid];
        float w3 = W[(k + 3) * D + tid];
        unsigned long long wA = pack2(w0, w1);
        unsigned long long wB = pack2(w2, w3);
        #pragma unroll
        for (int r = 0; r < TILE_ROWS; r++) {
            ulonglong2 a2 = *reinterpret_cast<const ulonglong2*>(&sA[r][k]);  // LDS.128 bcast
            fma2(acc2[r], a2.x, wA);
            fma2(acc2[r], a2.y, wB);
        }
    }

    const float bb = b[tid];
    const float pa = *prelu_a;
    #pragma unroll
    for (int r = 0; r < TILE_ROWS; r++) {
        int gr = base + r;
        float2 p = unpack2(acc2[r]);
        float z = p.x + p.y + bb;
        z = (z >= 0.f) ? z : pa * z;
        if (ROW_SCALE) z *= __ldg(&inv[gr]);   // pre-scale for next layer's gather
        out[(size_t)gr * D + tid] = z;
    }
}

// ---------------------------------------------------------------------------
// Launch sequence (graph-capturable, idempotent)
// ---------------------------------------------------------------------------
extern "C" void kernel_launch(void* const* d_in, const int* in_sizes, int n_in,
                              void* d_out, int out_size) {
    const float* x   = (const float*)d_in[0];
    const int*   src = (const int*)  d_in[1];
    const int*   dst = (const int*)  d_in[2];
    const float* W1  = (const float*)d_in[3];
    const float* b1  = (const float*)d_in[4];
    const float* W2  = (const float*)d_in[5];
    const float* b2  = (const float*)d_in[6];
    const float* pa  = (const float*)d_in[7];
    float*       out = (float*)d_out;

    float *inv_p, *z1_p;
    int *counts_p, *cursor_p, *rowptr_p, *bsums_p, *eidx_p;
    cudaGetSymbolAddress((void**)&inv_p,    g_inv);
    cudaGetSymbolAddress((void**)&counts_p, g_counts);
    cudaGetSymbolAddress((void**)&cursor_p, g_cursor);
    cudaGetSymbolAddress((void**)&rowptr_p, g_rowptr);
    cudaGetSymbolAddress((void**)&bsums_p,  g_bsums);
    cudaGetSymbolAddress((void**)&eidx_p,   g_eidx);
    cudaGetSymbolAddress((void**)&z1_p,     g_z1);

    const int TB = 256;
    const int node_grid = (N_NODES + TB - 1) / TB;
    const int edge_grid = (N_EDGES + TB - 1) / TB;

    // 1) degree + CSR build
    zero_small_kernel<<<node_grid, TB>>>(inv_p, counts_p, cursor_p);
    hist_kernel<<<edge_grid, TB>>>(src, dst, inv_p, counts_p);
    inv_kernel<<<node_grid, TB>>>(inv_p);
    scan_block_kernel<<<N_SCANBLK, SCAN_B>>>(counts_p, rowptr_p, bsums_p);
    scan_sums_kernel<<<1, 128>>>(bsums_p);
    scan_add_kernel<<<N_SCANBLK, SCAN_B>>>(rowptr_p, bsums_p);
    csr_fill_kernel<<<edge_grid, TB>>>(src, dst, rowptr_p, cursor_p, eidx_p);

    const int fused_grid = N_NODES / TILE_ROWS;   // 3125, exact

    // 2) Layer 1: gather(x * inv[src]) -> W1 -> prelu -> * inv[dst] -> z1
    fused_layer_kernel<true, true><<<fused_grid, 128>>>(
        x, rowptr_p, eidx_p, inv_p, W1, b1, pa, z1_p);

    // 3) Layer 2: gather(z1) -> W2 -> prelu -> out
    fused_layer_kernel<false, false><<<fused_grid, 128>>>(
        z1_p, rowptr_p, eidx_p, inv_p, W2, b2, pa, out);
}